// round 14
// baseline (speedup 1.0000x reference)
#include <cuda_runtime.h>
#include <cuda_fp16.h>
#include <cstdint>
#include <math.h>

#define MAXN 100000
#define MAXE 1000000
#define HF   64
#define NPW  16          // nodes per warp in agg_pool
#define SBLK 1024        // scan block size

// ---------------- scratch (device globals; zero-initialized at load) ------------
__device__ __align__(16) float4 g_acc[MAXN];      // {degw_edges, cnt, den, num}; zeroed by k_scan
__device__ __align__(16) float  g_dis[MAXN];
__device__ __align__(16) float  g_nw[MAXN];
__device__ __align__(16) int    g_cnt2[MAXN];     // scatter cursor
__device__ __align__(16) int    g_state[128];     // lookback scan flags; reset by k_setup
__device__ __align__(16) int    g_offs[MAXN + 1];
__device__ __align__(16) float2 g_edge[MAXE];     // .x = src (int bits), .y = norm
__device__ __align__(16) __half g_tA[(size_t)MAXN * HF];
__device__ __align__(16) __half g_tB[(size_t)MAXN * HF];
__device__ __align__(16) float  g_s[256 * HF];    // zeroed by k_head after use
__device__ __align__(16) float  g_wsum[256];      // zeroed by k_head after use

// ---------------- tensor-core mma.sync m16n8k16 (fp16 x fp16 -> fp32) ----------
__device__ __forceinline__ void mma16816(float* c,
                                         uint32_t a0, uint32_t a1, uint32_t a2, uint32_t a3,
                                         uint32_t b0, uint32_t b1) {
    asm volatile(
        "mma.sync.aligned.m16n8k16.row.col.f32.f16.f16.f32 "
        "{%0,%1,%2,%3}, {%4,%5,%6,%7}, {%8,%9}, {%0,%1,%2,%3};"
        : "+f"(c[0]), "+f"(c[1]), "+f"(c[2]), "+f"(c[3])
        : "r"(a0), "r"(a1), "r"(a2), "r"(a3), "r"(b0), "r"(b1));
}

// ---- aggregate loop with one-ahead edge prefetch (breaks edge->gather chain) ----
// Edge records are streamed with __ldcs (read-once); the gather for iteration i
// uses an edge value loaded during iteration i-1, so the per-iteration critical
// path is only the feature gather.
#define AGG_LOOP(node, ax, ay)                                                      \
    {                                                                               \
        int p = g_offs[node], end = g_offs[(node) + 1];                             \
        if (p < end) {                                                              \
            float2 pk = __ldcs(&g_edge[p]);                                         \
            for (++p; p < end; ++p) {                                               \
                float2 pknext = __ldcs(&g_edge[p]);                                 \
                float2 v = __half22float2(tmp[(size_t)__float_as_int(pk.x) * 32 + lane]); \
                ax += pk.y * v.x;                                                   \
                ay += pk.y * v.y;                                                   \
                pk = pknext;                                                        \
            }                                                                       \
            float2 v = __half22float2(tmp[(size_t)__float_as_int(pk.x) * 32 + lane]); \
            ax += pk.y * v.x;                                                       \
            ay += pk.y * v.y;                                                       \
        }                                                                           \
    }

// ---------------- L0: fused edge accumulation + layer-1 GEMM + flag reset -------
__global__ void k_setup(const int* __restrict__ row, const int* __restrict__ col,
                        const float* __restrict__ ew, int e,
                        const float* __restrict__ x, const float* __restrict__ W1,
                        __half* __restrict__ C, int n, int gemmBlks) {
    if ((int)blockIdx.x >= gemmBlks) {
        int i = ((int)blockIdx.x - gemmBlks) * blockDim.x + threadIdx.x;
        if (i >= e) return;
        int r = row[i], c = col[i];
        float w = ew[i];
        float a = __expf((w - 1.0f) * 20.0f);      // softmax shift-invariant, w in [0,1)
        float wa = w * a;
        atomicAdd(&g_acc[c], make_float4(w, 1.0f, a, wa));         // 16B RED
        atomicAdd(((float2*)&g_acc[r]) + 1, make_float2(a, wa));   // 8B RED on .zw
        return;
    }
    if (blockIdx.x == 0 && threadIdx.x < 128) g_state[threadIdx.x] = 0;  // reset lookback flags

    __shared__ float As[64][65];
    __shared__ float Ws[64][64];
    int brow = blockIdx.x * 64;
    for (int i = threadIdx.x; i < 4096; i += 256) {
        int rr = i >> 6, cc = i & 63;
        Ws[rr][cc] = W1[i];
        int gr = brow + rr;
        As[rr][cc] = (gr < n) ? x[(size_t)gr * HF + cc] : 0.0f;
    }
    __syncthreads();
    int r0 = (threadIdx.x >> 4) * 4;
    int c0 = (threadIdx.x & 15) * 4;
    float acc[4][4] = {};
#pragma unroll
    for (int k = 0; k < 64; k++) {
        float a0 = As[r0 + 0][k], a1 = As[r0 + 1][k], a2 = As[r0 + 2][k], a3 = As[r0 + 3][k];
        float4 w4 = *(const float4*)&Ws[k][c0];
        acc[0][0] += a0 * w4.x; acc[0][1] += a0 * w4.y; acc[0][2] += a0 * w4.z; acc[0][3] += a0 * w4.w;
        acc[1][0] += a1 * w4.x; acc[1][1] += a1 * w4.y; acc[1][2] += a1 * w4.z; acc[1][3] += a1 * w4.w;
        acc[2][0] += a2 * w4.x; acc[2][1] += a2 * w4.y; acc[2][2] += a2 * w4.z; acc[2][3] += a2 * w4.w;
        acc[3][0] += a3 * w4.x; acc[3][1] += a3 * w4.y; acc[3][2] += a3 * w4.z; acc[3][3] += a3 * w4.w;
    }
#pragma unroll
    for (int i = 0; i < 4; i++) {
        int gr = brow + r0 + i;
        if (gr < n) {
            __half2* dst = (__half2*)&C[(size_t)gr * HF + c0];
            dst[0] = __floats2half2_rn(acc[i][0], acc[i][1]);
            dst[1] = __floats2half2_rn(acc[i][2], acc[i][3]);
        }
    }
}

// ---------------- L1: single-pass decoupled-lookback scan + node finish ---------
__global__ void k_scan(int n, int e) {
    __shared__ int wsum[32];
    __shared__ int s_prefix;
    int i = blockIdx.x * SBLK + threadIdx.x;
    int lane = threadIdx.x & 31;
    int wid = threadIdx.x >> 5;
    int v = 0;
    if (i < n) {
        float4 ac = g_acc[i];
        v = (int)ac.y;
        g_dis[i] = rsqrtf(1.0f + ac.x);             // self-loop weight 1 added here
        g_nw[i] = (ac.z > 0.0f) ? ac.w / fmaxf(ac.z, 1e-16f) : 0.0f;
        g_acc[i] = make_float4(0.0f, 0.0f, 0.0f, 0.0f);   // reset for next replay
    }
    int s = v;
#pragma unroll
    for (int o = 1; o < 32; o <<= 1) {
        int t = __shfl_up_sync(0xFFFFFFFFu, s, o);
        if (lane >= o) s += t;
    }
    if (lane == 31) wsum[wid] = s;
    __syncthreads();
    if (wid == 0) {
        int ws = wsum[lane];
#pragma unroll
        for (int o = 1; o < 32; o <<= 1) {
            int t = __shfl_up_sync(0xFFFFFFFFu, ws, o);
            if (lane >= o) ws += t;
        }
        wsum[lane] = ws;
    }
    __syncthreads();
    int incl = s + (wid > 0 ? wsum[wid - 1] : 0);
    int blockAgg = wsum[31];

    if (threadIdx.x == 0) {
        int b = blockIdx.x;
        if (b == 0) {
            atomicExch(&g_state[0], (blockAgg << 2) | 2);
            s_prefix = 0;
        } else {
            atomicExch(&g_state[b], (blockAgg << 2) | 1);
            int prefix = 0;
            int j = b - 1;
            while (j >= 0) {
                int st = atomicAdd(&g_state[j], 0);
                int status = st & 3;
                if (status == 2) { prefix += (st >> 2); break; }
                if (status == 1) { prefix += (st >> 2); j--; }
            }
            atomicExch(&g_state[b], ((prefix + blockAgg) << 2) | 2);
            s_prefix = prefix;
        }
    }
    __syncthreads();
    int prefix = s_prefix;
    if (i < n) {
        int o = prefix + incl - v;
        g_offs[i] = o;
        g_cnt2[i] = o;
    }
    if (i == 0) g_offs[n] = e;
}

// ---------------- L2: scatter edges into destination-sorted order ---------------
__global__ void k_edge_scatter(const int* __restrict__ row, const int* __restrict__ col,
                               const float* __restrict__ ew, int e) {
    int i = blockIdx.x * blockDim.x + threadIdx.x;
    if (i >= e) return;
    int r = row[i], c = col[i];
    int p = atomicAdd(&g_cnt2[c], 1);
    float2 pk;
    pk.x = __int_as_float(r);
    pk.y = g_dis[r] * ew[i] * g_dis[c];
    g_edge[p] = pk;
}

// ---------------- L3/L4: fused aggregate(+bias+LeakyReLU) -> TC GEMM ------------
__global__ __launch_bounds__(256) void k_agg_gemm(
        const __half2* __restrict__ tmp, const float* __restrict__ bias,
        const float* __restrict__ W, __half* __restrict__ C, int n) {
    __shared__ __half As[64][72];                  // stride 72 halves: conflict-free
    __shared__ __half Wt[64][72];                  // transposed W: Wt[n][k]
    int brow = blockIdx.x * 64;
    int wid = threadIdx.x >> 5;
    int lane = threadIdx.x & 31;

    // W[k][n] fp32 -> Wt[n][k] fp16 (coalesced global reads)
    for (int i = threadIdx.x; i < 4096; i += 256) {
        int k = i >> 6, nn = i & 63;
        Wt[nn][k] = __float2half(W[i]);
    }

    float2 bb = ((const float2*)bias)[lane];
#pragma unroll
    for (int j = 0; j < 8; j++) {
        int rr = wid * 8 + j;
        int node = brow + rr;
        float ax = 0.0f, ay = 0.0f;
        if (node < n) {
            float d = g_dis[node];
            float sc = d * d;
            float2 self = __half22float2(tmp[(size_t)node * 32 + lane]);
            ax = sc * self.x;
            ay = sc * self.y;
            AGG_LOOP(node, ax, ay)
            ax += bb.x; ay += bb.y;
            ax = (ax > 0.0f) ? ax : 0.01f * ax;     // LeakyReLU
            ay = (ay > 0.0f) ? ay : 0.01f * ay;
        }
        *(__half2*)&As[rr][2 * lane] = __floats2half2_rn(ax, ay);
    }
    __syncthreads();

    // --- tensor-core GEMM: As[64x64] @ Wt^T -> C[64x64] ---
    int tr = (wid & 3) << 4;                       // row strip: 0/16/32/48
    int tc = (wid >> 2) << 5;                      // col half:  0/32
    int qr = lane >> 2;                            // 0..7
    int qc = (lane & 3) << 1;                      // 0,2,4,6
    float acc[4][4];
#pragma unroll
    for (int t = 0; t < 4; t++)
#pragma unroll
        for (int j = 0; j < 4; j++) acc[t][j] = 0.0f;

#pragma unroll
    for (int k = 0; k < 64; k += 16) {
        uint32_t a0 = *(const uint32_t*)&As[tr + qr][k + qc];
        uint32_t a1 = *(const uint32_t*)&As[tr + qr + 8][k + qc];
        uint32_t a2 = *(const uint32_t*)&As[tr + qr][k + qc + 8];
        uint32_t a3 = *(const uint32_t*)&As[tr + qr + 8][k + qc + 8];
#pragma unroll
        for (int t = 0; t < 4; t++) {
            const __half* bp = &Wt[tc + t * 8 + qr][k + qc];
            uint32_t b0 = *(const uint32_t*)bp;
            uint32_t b1 = *(const uint32_t*)(bp + 8);
            mma16816(acc[t], a0, a1, a2, a3, b0, b1);
        }
    }
#pragma unroll
    for (int t = 0; t < 4; t++) {
        int colo = tc + t * 8 + qc;
        int gr0 = brow + tr + qr;
        if (gr0 < n)
            *(__half2*)&C[(size_t)gr0 * HF + colo] = __floats2half2_rn(acc[t][0], acc[t][1]);
        if (gr0 + 8 < n)
            *(__half2*)&C[(size_t)(gr0 + 8) * HF + colo] = __floats2half2_rn(acc[t][2], acc[t][3]);
    }
}

// ---------------- L5: fused layer-3 aggregation + weighted pooling --------------
__global__ void k_agg_pool(const __half2* __restrict__ tmp, const float* __restrict__ bias,
                           const int* __restrict__ batch, int n) {
    int warp = (blockIdx.x * blockDim.x + threadIdx.x) >> 5;
    int lane = threadIdx.x & 31;
    int n0 = warp * NPW;
    if (n0 >= n) return;
    int n1 = min(n0 + NPW, n);
    float2 bb = ((const float2*)bias)[lane];
    float px = 0.0f, py = 0.0f, wacc = 0.0f;
    int cb = batch[n0];
    for (int node = n0; node < n1; node++) {
        int b = batch[node];
        if (b != cb) {
            atomicAdd(&g_s[cb * HF + 2 * lane],     px);
            atomicAdd(&g_s[cb * HF + 2 * lane + 1], py);
            if (lane == 0) atomicAdd(&g_wsum[cb], wacc);
            px = py = wacc = 0.0f;
            cb = b;
        }
        float d = g_dis[node];
        float sc = d * d;
        float2 self = __half22float2(tmp[(size_t)node * 32 + lane]);
        float ax = sc * self.x;
        float ay = sc * self.y;
        AGG_LOOP(node, ax, ay)
        float nwv = g_nw[node];
        px += nwv * (ax + bb.x);
        py += nwv * (ay + bb.y);
        wacc += nwv;
    }
    atomicAdd(&g_s[cb * HF + 2 * lane],     px);
    atomicAdd(&g_s[cb * HF + 2 * lane + 1], py);
    if (lane == 0) atomicAdd(&g_wsum[cb], wacc);
}

// ---------------- L6: MLP head; self-cleans g_s/g_wsum --------------------------
__global__ void k_head(const float* __restrict__ Wlin, const float* __restrict__ blin,
                       const float* __restrict__ Wout, const float* __restrict__ bout,
                       float* __restrict__ out, int bn) {
    int b = blockIdx.x * blockDim.x + threadIdx.x;
    if (b >= bn) return;
    const int O_PROBS = bn * 10;
    const int O_FEATS = bn * 20;
    const int O_EMB   = O_FEATS + bn * 128;
    const int O_HOUT  = O_EMB + bn * 64;

    float feats[128];
    float ws = fmaxf(g_wsum[b], 1e-16f);
#pragma unroll
    for (int k = 0; k < HF; k++) {
        float sv = g_s[b * HF + k];
        feats[k] = sv;
        feats[HF + k] = sv / ws;
        g_s[b * HF + k] = 0.0f;
    }
    g_wsum[b] = 0.0f;

    float emb[64], ho[64];
    for (int j = 0; j < 64; j++) {
        float a = blin[j];
        for (int i = 0; i < 128; i++) a += feats[i] * __ldg(&Wlin[i * 64 + j]);
        emb[j] = a;
        ho[j] = fmaxf(a, 0.0f);
    }
    float lg[10];
    for (int c = 0; c < 10; c++) {
        float a = bout[c];
        for (int j = 0; j < 64; j++) a += ho[j] * __ldg(&Wout[j * 10 + c]);
        lg[c] = a;
    }
    float mx = lg[0];
#pragma unroll
    for (int c = 1; c < 10; c++) mx = fmaxf(mx, lg[c]);
    float ex[10], den = 0.0f;
#pragma unroll
    for (int c = 0; c < 10; c++) { ex[c] = expf(lg[c] - mx); den += ex[c]; }
    float inv = 1.0f / den;

    for (int c = 0; c < 10; c++) {
        out[b * 10 + c] = lg[c];
        out[O_PROBS + b * 10 + c] = ex[c] * inv;
    }
    for (int i = 0; i < 128; i++) out[O_FEATS + b * 128 + i] = feats[i];
    for (int j = 0; j < 64; j++) {
        out[O_EMB  + b * 64 + j] = emb[j];
        out[O_HOUT + b * 64 + j] = ho[j];
    }
}

// ---------------------------------------------------------------------------------
extern "C" void kernel_launch(void* const* d_in, const int* in_sizes, int n_in,
                              void* d_out, int out_size) {
    const float* x    = (const float*)d_in[0];
    const int*   ei   = (const int*)  d_in[1];
    const float* ew   = (const float*)d_in[2];
    const int*   batch= (const int*)  d_in[3];
    const float* W1 = (const float*)d_in[4];  const float* b1 = (const float*)d_in[5];
    const float* W2 = (const float*)d_in[6];  const float* b2 = (const float*)d_in[7];
    const float* W3 = (const float*)d_in[8];  const float* b3 = (const float*)d_in[9];
    const float* Wlin = (const float*)d_in[10]; const float* blin = (const float*)d_in[11];
    const float* Wout = (const float*)d_in[12]; const float* bout = (const float*)d_in[13];
    float* out = (float*)d_out;

    int n  = in_sizes[0] / HF;
    int e  = in_sizes[2];
    int bn = out_size / 276;

    const int* row = ei;
    const int* col = ei + e;

    __half *p_tA, *p_tB;
    cudaGetSymbolAddress((void**)&p_tA, g_tA);
    cudaGetSymbolAddress((void**)&p_tB, g_tB);

    const int T = 256;
    int nBlkE = (e + T - 1) / T;
    int nBlkP = ((((n + NPW - 1) / NPW) * 32) + T - 1) / T;
    int nb = (n + SBLK - 1) / SBLK;
    int gemmBlks = (n + 63) / 64;

    // L0: fused edge accumulation + layer-1 GEMM + scan-flag reset
    k_setup<<<gemmBlks + nBlkE, T>>>(row, col, ew, e, x, W1, p_tA, n, gemmBlks);
    // L1: single-pass scan + node finish
    k_scan<<<nb, SBLK>>>(n, e);
    // L2: counting-sort scatter
    k_edge_scatter<<<nBlkE, T>>>(row, col, ew, e);
    // L3 (PROFILED): layer-1 aggregate + layer-2 TC GEMM
    k_agg_gemm<<<gemmBlks, 256>>>((const __half2*)p_tA, b1, W2, p_tB, n);
    // L4: layer-2 aggregate + layer-3 TC GEMM
    k_agg_gemm<<<gemmBlks, 256>>>((const __half2*)p_tB, b2, W3, p_tA, n);
    // L5: layer-3 aggregate + pooling
    k_agg_pool<<<nBlkP, T>>>((const __half2*)p_tA, b3, batch, n);
    // L6: head
    k_head<<<(bn + 127) / 128, 128>>>(Wlin, blin, Wout, bout, out, bn);
}

// round 15
// speedup vs baseline: 1.0161x; 1.0161x over previous
#include <cuda_runtime.h>
#include <cuda_fp16.h>
#include <cstdint>
#include <math.h>

#define MAXN 100000
#define MAXE 1000000
#define HF   64
#define NPW  16          // nodes per warp in agg_pool
#define SBLK 1024        // scan block size

// ---------------- scratch (device globals; zero-initialized at load) ------------
__device__ __align__(16) float4 g_acc[MAXN];      // {degw_edges, cnt, den, num}; zeroed by k_scan
__device__ __align__(16) float  g_dis[MAXN];
__device__ __align__(16) float  g_nw[MAXN];
__device__ __align__(16) int    g_cnt2[MAXN];     // scatter cursor
__device__ __align__(16) int    g_state[128];     // lookback scan flags; reset by k_setup
__device__ __align__(16) int    g_offs[MAXN + 1];
__device__ __align__(16) float2 g_edge[MAXE];     // .x = src (int bits), .y = norm
__device__ __align__(16) __half g_tA[(size_t)MAXN * HF];
__device__ __align__(16) __half g_tB[(size_t)MAXN * HF];
__device__ __align__(16) float  g_s[256 * HF];    // zeroed by k_head after use
__device__ __align__(16) float  g_wsum[256];      // zeroed by k_head after use

// ---------------- tensor-core mma.sync m16n8k16 (fp16 x fp16 -> fp32) ----------
__device__ __forceinline__ void mma16816(float* c,
                                         uint32_t a0, uint32_t a1, uint32_t a2, uint32_t a3,
                                         uint32_t b0, uint32_t b1) {
    asm volatile(
        "mma.sync.aligned.m16n8k16.row.col.f32.f16.f16.f32 "
        "{%0,%1,%2,%3}, {%4,%5,%6,%7}, {%8,%9}, {%0,%1,%2,%3};"
        : "+f"(c[0]), "+f"(c[1]), "+f"(c[2]), "+f"(c[3])
        : "r"(a0), "r"(a1), "r"(a2), "r"(a3), "r"(b0), "r"(b1));
}

// ---------------- L0: fused edge accumulation + layer-1 GEMM + flag reset -------
__global__ void k_setup(const int* __restrict__ row, const int* __restrict__ col,
                        const float* __restrict__ ew, int e,
                        const float* __restrict__ x, const float* __restrict__ W1,
                        __half* __restrict__ C, int n, int gemmBlks) {
    if ((int)blockIdx.x >= gemmBlks) {
        int i = ((int)blockIdx.x - gemmBlks) * blockDim.x + threadIdx.x;
        if (i >= e) return;
        int r = row[i], c = col[i];
        float w = ew[i];
        float a = __expf((w - 1.0f) * 20.0f);      // softmax shift-invariant, w in [0,1)
        float wa = w * a;
        atomicAdd(&g_acc[c], make_float4(w, 1.0f, a, wa));         // 16B RED
        atomicAdd(((float2*)&g_acc[r]) + 1, make_float2(a, wa));   // 8B RED on .zw
        return;
    }
    if (blockIdx.x == 0 && threadIdx.x < 128) g_state[threadIdx.x] = 0;  // reset lookback flags

    __shared__ float As[64][65];
    __shared__ float Ws[64][64];
    int brow = blockIdx.x * 64;
    for (int i = threadIdx.x; i < 4096; i += 256) {
        int rr = i >> 6, cc = i & 63;
        Ws[rr][cc] = W1[i];
        int gr = brow + rr;
        As[rr][cc] = (gr < n) ? x[(size_t)gr * HF + cc] : 0.0f;
    }
    __syncthreads();
    int r0 = (threadIdx.x >> 4) * 4;
    int c0 = (threadIdx.x & 15) * 4;
    float acc[4][4] = {};
#pragma unroll
    for (int k = 0; k < 64; k++) {
        float a0 = As[r0 + 0][k], a1 = As[r0 + 1][k], a2 = As[r0 + 2][k], a3 = As[r0 + 3][k];
        float4 w4 = *(const float4*)&Ws[k][c0];
        acc[0][0] += a0 * w4.x; acc[0][1] += a0 * w4.y; acc[0][2] += a0 * w4.z; acc[0][3] += a0 * w4.w;
        acc[1][0] += a1 * w4.x; acc[1][1] += a1 * w4.y; acc[1][2] += a1 * w4.z; acc[1][3] += a1 * w4.w;
        acc[2][0] += a2 * w4.x; acc[2][1] += a2 * w4.y; acc[2][2] += a2 * w4.z; acc[2][3] += a2 * w4.w;
        acc[3][0] += a3 * w4.x; acc[3][1] += a3 * w4.y; acc[3][2] += a3 * w4.z; acc[3][3] += a3 * w4.w;
    }
#pragma unroll
    for (int i = 0; i < 4; i++) {
        int gr = brow + r0 + i;
        if (gr < n) {
            __half2* dst = (__half2*)&C[(size_t)gr * HF + c0];
            dst[0] = __floats2half2_rn(acc[i][0], acc[i][1]);
            dst[1] = __floats2half2_rn(acc[i][2], acc[i][3]);
        }
    }
}

// ---------------- L1: single-pass decoupled-lookback scan + node finish ---------
__global__ void k_scan(int n, int e) {
    __shared__ int wsum[32];
    __shared__ int s_prefix;
    int i = blockIdx.x * SBLK + threadIdx.x;
    int lane = threadIdx.x & 31;
    int wid = threadIdx.x >> 5;
    int v = 0;
    if (i < n) {
        float4 ac = g_acc[i];
        v = (int)ac.y;
        g_dis[i] = rsqrtf(1.0f + ac.x);             // self-loop weight 1 added here
        g_nw[i] = (ac.z > 0.0f) ? ac.w / fmaxf(ac.z, 1e-16f) : 0.0f;
        g_acc[i] = make_float4(0.0f, 0.0f, 0.0f, 0.0f);   // reset for next replay
    }
    int s = v;
#pragma unroll
    for (int o = 1; o < 32; o <<= 1) {
        int t = __shfl_up_sync(0xFFFFFFFFu, s, o);
        if (lane >= o) s += t;
    }
    if (lane == 31) wsum[wid] = s;
    __syncthreads();
    if (wid == 0) {
        int ws = wsum[lane];
#pragma unroll
        for (int o = 1; o < 32; o <<= 1) {
            int t = __shfl_up_sync(0xFFFFFFFFu, ws, o);
            if (lane >= o) ws += t;
        }
        wsum[lane] = ws;
    }
    __syncthreads();
    int incl = s + (wid > 0 ? wsum[wid - 1] : 0);
    int blockAgg = wsum[31];

    if (threadIdx.x == 0) {
        int b = blockIdx.x;
        if (b == 0) {
            atomicExch(&g_state[0], (blockAgg << 2) | 2);
            s_prefix = 0;
        } else {
            atomicExch(&g_state[b], (blockAgg << 2) | 1);
            int prefix = 0;
            int j = b - 1;
            while (j >= 0) {
                int st = atomicAdd(&g_state[j], 0);
                int status = st & 3;
                if (status == 2) { prefix += (st >> 2); break; }
                if (status == 1) { prefix += (st >> 2); j--; }
            }
            atomicExch(&g_state[b], ((prefix + blockAgg) << 2) | 2);
            s_prefix = prefix;
        }
    }
    __syncthreads();
    int prefix = s_prefix;
    if (i < n) {
        int o = prefix + incl - v;
        g_offs[i] = o;
        g_cnt2[i] = o;
    }
    if (i == 0) g_offs[n] = e;
}

// ---------------- L2: scatter edges into destination-sorted order ---------------
__global__ void k_edge_scatter(const int* __restrict__ row, const int* __restrict__ col,
                               const float* __restrict__ ew, int e) {
    int i = blockIdx.x * blockDim.x + threadIdx.x;
    if (i >= e) return;
    int r = row[i], c = col[i];
    int p = atomicAdd(&g_cnt2[c], 1);
    float2 pk;
    pk.x = __int_as_float(r);
    pk.y = g_dis[r] * ew[i] * g_dis[c];
    g_edge[p] = pk;
}

// ---------------- L3/L4: fused aggregate(+bias+LeakyReLU) -> TC GEMM ------------
// Aggregate phase: warp-per-node serial gather (proven optimal across 4 probes).
// GEMM phase: mma.sync.m16n8k16, 8 warps x (16-row strip, 32-col half), K=64.
__global__ __launch_bounds__(256) void k_agg_gemm(
        const __half2* __restrict__ tmp, const float* __restrict__ bias,
        const float* __restrict__ W, __half* __restrict__ C, int n) {
    __shared__ __half As[64][72];                  // stride 72 halves: conflict-free
    __shared__ __half Wt[64][72];                  // transposed W: Wt[n][k]
    int brow = blockIdx.x * 64;
    int wid = threadIdx.x >> 5;
    int lane = threadIdx.x & 31;

    // W[k][n] fp32 -> Wt[n][k] fp16 (coalesced global reads)
    for (int i = threadIdx.x; i < 4096; i += 256) {
        int k = i >> 6, nn = i & 63;
        Wt[nn][k] = __float2half(W[i]);
    }

    float2 bb = ((const float2*)bias)[lane];
#pragma unroll
    for (int j = 0; j < 8; j++) {
        int rr = wid * 8 + j;
        int node = brow + rr;
        float ax = 0.0f, ay = 0.0f;
        if (node < n) {
            float d = g_dis[node];
            float sc = d * d;
            float2 self = __half22float2(tmp[(size_t)node * 32 + lane]);
            ax = sc * self.x;
            ay = sc * self.y;
            int p = g_offs[node], end = g_offs[node + 1];
            for (; p < end; ++p) {
                float2 pk = g_edge[p];
                int s = __float_as_int(pk.x);
                float2 v = __half22float2(tmp[(size_t)s * 32 + lane]);
                ax += pk.y * v.x;
                ay += pk.y * v.y;
            }
            ax += bb.x; ay += bb.y;
            ax = (ax > 0.0f) ? ax : 0.01f * ax;     // LeakyReLU
            ay = (ay > 0.0f) ? ay : 0.01f * ay;
        }
        *(__half2*)&As[rr][2 * lane] = __floats2half2_rn(ax, ay);
    }
    __syncthreads();

    // --- tensor-core GEMM: As[64x64] @ Wt^T -> C[64x64] ---
    int tr = (wid & 3) << 4;                       // row strip: 0/16/32/48
    int tc = (wid >> 2) << 5;                      // col half:  0/32
    int qr = lane >> 2;                            // 0..7
    int qc = (lane & 3) << 1;                      // 0,2,4,6
    float acc[4][4];
#pragma unroll
    for (int t = 0; t < 4; t++)
#pragma unroll
        for (int j = 0; j < 4; j++) acc[t][j] = 0.0f;

#pragma unroll
    for (int k = 0; k < 64; k += 16) {
        uint32_t a0 = *(const uint32_t*)&As[tr + qr][k + qc];
        uint32_t a1 = *(const uint32_t*)&As[tr + qr + 8][k + qc];
        uint32_t a2 = *(const uint32_t*)&As[tr + qr][k + qc + 8];
        uint32_t a3 = *(const uint32_t*)&As[tr + qr + 8][k + qc + 8];
#pragma unroll
        for (int t = 0; t < 4; t++) {
            const __half* bp = &Wt[tc + t * 8 + qr][k + qc];
            uint32_t b0 = *(const uint32_t*)bp;
            uint32_t b1 = *(const uint32_t*)(bp + 8);
            mma16816(acc[t], a0, a1, a2, a3, b0, b1);
        }
    }
#pragma unroll
    for (int t = 0; t < 4; t++) {
        int colo = tc + t * 8 + qc;
        int gr0 = brow + tr + qr;
        if (gr0 < n)
            *(__half2*)&C[(size_t)gr0 * HF + colo] = __floats2half2_rn(acc[t][0], acc[t][1]);
        if (gr0 + 8 < n)
            *(__half2*)&C[(size_t)(gr0 + 8) * HF + colo] = __floats2half2_rn(acc[t][2], acc[t][3]);
    }
}

// ---------------- L5: fused layer-3 aggregation + weighted pooling --------------
__global__ void k_agg_pool(const __half2* __restrict__ tmp, const float* __restrict__ bias,
                           const int* __restrict__ batch, int n) {
    int warp = (blockIdx.x * blockDim.x + threadIdx.x) >> 5;
    int lane = threadIdx.x & 31;
    int n0 = warp * NPW;
    if (n0 >= n) return;
    int n1 = min(n0 + NPW, n);
    float2 bb = ((const float2*)bias)[lane];
    float px = 0.0f, py = 0.0f, wacc = 0.0f;
    int cb = batch[n0];
    for (int node = n0; node < n1; node++) {
        int b = batch[node];
        if (b != cb) {
            atomicAdd(&g_s[cb * HF + 2 * lane],     px);
            atomicAdd(&g_s[cb * HF + 2 * lane + 1], py);
            if (lane == 0) atomicAdd(&g_wsum[cb], wacc);
            px = py = wacc = 0.0f;
            cb = b;
        }
        float d = g_dis[node];
        float sc = d * d;
        float2 self = __half22float2(tmp[(size_t)node * 32 + lane]);
        float ax = sc * self.x;
        float ay = sc * self.y;
        int p = g_offs[node], end = g_offs[node + 1];
        for (; p < end; ++p) {
            float2 pk = g_edge[p];
            int s = __float_as_int(pk.x);
            float2 v = __half22float2(tmp[(size_t)s * 32 + lane]);
            ax += pk.y * v.x;
            ay += pk.y * v.y;
        }
        float nwv = g_nw[node];
        px += nwv * (ax + bb.x);
        py += nwv * (ay + bb.y);
        wacc += nwv;
    }
    atomicAdd(&g_s[cb * HF + 2 * lane],     px);
    atomicAdd(&g_s[cb * HF + 2 * lane + 1], py);
    if (lane == 0) atomicAdd(&g_wsum[cb], wacc);
}

// ---------------- L6: MLP head; self-cleans g_s/g_wsum --------------------------
__global__ void k_head(const float* __restrict__ Wlin, const float* __restrict__ blin,
                       const float* __restrict__ Wout, const float* __restrict__ bout,
                       float* __restrict__ out, int bn) {
    int b = blockIdx.x * blockDim.x + threadIdx.x;
    if (b >= bn) return;
    const int O_PROBS = bn * 10;
    const int O_FEATS = bn * 20;
    const int O_EMB   = O_FEATS + bn * 128;
    const int O_HOUT  = O_EMB + bn * 64;

    float feats[128];
    float ws = fmaxf(g_wsum[b], 1e-16f);
#pragma unroll
    for (int k = 0; k < HF; k++) {
        float sv = g_s[b * HF + k];
        feats[k] = sv;
        feats[HF + k] = sv / ws;
        g_s[b * HF + k] = 0.0f;
    }
    g_wsum[b] = 0.0f;

    float emb[64], ho[64];
    for (int j = 0; j < 64; j++) {
        float a = blin[j];
        for (int i = 0; i < 128; i++) a += feats[i] * __ldg(&Wlin[i * 64 + j]);
        emb[j] = a;
        ho[j] = fmaxf(a, 0.0f);
    }
    float lg[10];
    for (int c = 0; c < 10; c++) {
        float a = bout[c];
        for (int j = 0; j < 64; j++) a += ho[j] * __ldg(&Wout[j * 10 + c]);
        lg[c] = a;
    }
    float mx = lg[0];
#pragma unroll
    for (int c = 1; c < 10; c++) mx = fmaxf(mx, lg[c]);
    float ex[10], den = 0.0f;
#pragma unroll
    for (int c = 0; c < 10; c++) { ex[c] = expf(lg[c] - mx); den += ex[c]; }
    float inv = 1.0f / den;

    for (int c = 0; c < 10; c++) {
        out[b * 10 + c] = lg[c];
        out[O_PROBS + b * 10 + c] = ex[c] * inv;
    }
    for (int i = 0; i < 128; i++) out[O_FEATS + b * 128 + i] = feats[i];
    for (int j = 0; j < 64; j++) {
        out[O_EMB  + b * 64 + j] = emb[j];
        out[O_HOUT + b * 64 + j] = ho[j];
    }
}

// ---------------------------------------------------------------------------------
extern "C" void kernel_launch(void* const* d_in, const int* in_sizes, int n_in,
                              void* d_out, int out_size) {
    const float* x    = (const float*)d_in[0];
    const int*   ei   = (const int*)  d_in[1];
    const float* ew   = (const float*)d_in[2];
    const int*   batch= (const int*)  d_in[3];
    const float* W1 = (const float*)d_in[4];  const float* b1 = (const float*)d_in[5];
    const float* W2 = (const float*)d_in[6];  const float* b2 = (const float*)d_in[7];
    const float* W3 = (const float*)d_in[8];  const float* b3 = (const float*)d_in[9];
    const float* Wlin = (const float*)d_in[10]; const float* blin = (const float*)d_in[11];
    const float* Wout = (const float*)d_in[12]; const float* bout = (const float*)d_in[13];
    float* out = (float*)d_out;

    int n  = in_sizes[0] / HF;
    int e  = in_sizes[2];
    int bn = out_size / 276;

    const int* row = ei;
    const int* col = ei + e;

    __half *p_tA, *p_tB;
    cudaGetSymbolAddress((void**)&p_tA, g_tA);
    cudaGetSymbolAddress((void**)&p_tB, g_tB);

    const int T = 256;
    int nBlkE = (e + T - 1) / T;
    int nBlkP = ((((n + NPW - 1) / NPW) * 32) + T - 1) / T;
    int nb = (n + SBLK - 1) / SBLK;
    int gemmBlks = (n + 63) / 64;

    // L0: fused edge accumulation + layer-1 GEMM + scan-flag reset
    k_setup<<<gemmBlks + nBlkE, T>>>(row, col, ew, e, x, W1, p_tA, n, gemmBlks);
    // L1: single-pass scan + node finish
    k_scan<<<nb, SBLK>>>(n, e);
    // L2: counting-sort scatter
    k_edge_scatter<<<nBlkE, T>>>(row, col, ew, e);
    // L3: layer-1 aggregate + layer-2 TC GEMM
    k_agg_gemm<<<gemmBlks, 256>>>((const __half2*)p_tA, b1, W2, p_tB, n);
    // L4: layer-2 aggregate + layer-3 TC GEMM
    k_agg_gemm<<<gemmBlks, 256>>>((const __half2*)p_tB, b2, W3, p_tA, n);
    // L5: layer-3 aggregate + pooling
    k_agg_pool<<<nBlkP, T>>>((const __half2*)p_tA, b3, batch, n);
    // L6: head
    k_head<<<(bn + 127) / 128, 128>>>(Wlin, blin, Wout, bout, out, bn);
}